// round 9
// baseline (speedup 1.0000x reference)
#include <cuda_runtime.h>
#include <cstdint>
#include <math.h>

#define GO_TAG 1
#define NEGV   -10000.0f
#define K_     64
#define MAXELEMS_ (1024u * 512u * 64u)

typedef unsigned long long ull;

// Scratch: alpha history rows 1..len-1 per batch, trans tables.
__device__ float g_trans[K_ * K_];    // trans[i][j] = score(i -> j)
__device__ float g_transT[K_ * K_];   // transT[j][i] = trans[i][j]
__device__ float g_alpha[MAXELEMS_];

__device__ __forceinline__ void cp_async16(uint32_t saddr, const void* gptr) {
    asm volatile("cp.async.ca.shared.global [%0], [%1], 16;"
                 :: "r"(saddr), "l"(gptr));
}
__device__ __forceinline__ void cp_commit() {
    asm volatile("cp.async.commit_group;");
}
template <int N>
__device__ __forceinline__ void cp_wait() {
    asm volatile("cp.async.wait_group %0;" :: "n"(N));
}

// Packed f32x2 add (Blackwell): two independent f32 adds in one instruction.
__device__ __forceinline__ ull add2(ull a, ull b) {
    ull d;
    asm("add.rn.f32x2 %0, %1, %2;" : "=l"(d) : "l"(a), "l"(b));
    return d;
}
__device__ __forceinline__ void unpack2(ull s, float& lo, float& hi) {
    asm("mov.b64 {%0, %1}, %2;" : "=f"(lo), "=f"(hi) : "l"(s));
}

// ---------------------------------------------------------------------------
// Kernel 1: trans = log_softmax(A + mask * NEG, axis=-1) + transpose.
// ---------------------------------------------------------------------------
__global__ void __launch_bounds__(64)
trans_kernel(const float* __restrict__ c0, const float* __restrict__ c1) {
    __shared__ float  s_m[2];
    __shared__ double s_s[2];
    const int r = blockIdx.x;
    const int c = threadIdx.x;
    const int w = c >> 5;
    const int lane = c & 31;

    unsigned u0 = ((const unsigned*)c0)[r * K_ + c];
    const bool c0_is_mask = __syncthreads_and(u0 <= 1u);
    const int*   mask = (const int*)(c0_is_mask ? c0 : c1);
    const float* A    = c0_is_mask ? c1 : c0;

    float x = A[r * K_ + c] + (mask[r * K_ + c] ? NEGV : 0.0f);

    float m = x;
    #pragma unroll
    for (int d = 16; d > 0; d >>= 1) m = fmaxf(m, __shfl_xor_sync(~0u, m, d));
    if (lane == 0) s_m[w] = m;
    __syncthreads();
    m = fmaxf(s_m[0], s_m[1]);

    double e = exp((double)(x - m));
    #pragma unroll
    for (int d = 16; d > 0; d >>= 1) e += __shfl_xor_sync(~0u, e, d);
    if (lane == 0) s_s[w] = e;
    __syncthreads();
    const float l = (float)log(s_s[0] + s_s[1]);

    const float v = (x - m) - l;
    g_trans[r * K_ + c]  = v;
    g_transT[c * K_ + r] = v;
}

// ---------------------------------------------------------------------------
// Kernel 2: 1 sequence per 128-thread block (4 warps). Lanes (2k,2k+1) share
// tag j = 16*warp + k; each reduces half the i-range (32 candidates, packed
// adds), combined with one shfl_xor(1) + fmaxf. One __syncthreads per step.
// cp.async double-buffered staging for unary (fwd) and alpha history (bwd).
// ---------------------------------------------------------------------------
__global__ void __launch_bounds__(128)
viterbi_kernel(const float* __restrict__ unary,
               const int* __restrict__ lengths,
               float* __restrict__ out,
               int T, int B) {
    __shared__ __align__(16) float s_transT[K_ * K_];
    __shared__ __align__(16) float s_alpha[2][K_];   // [buf][j]
    __shared__ __align__(16) float s_u[2][8][K_];    // [buf][s][j]
    __shared__ int s_last;

    const int tid = threadIdx.x;
    const int lane = tid & 31;
    const int j = ((tid >> 5) << 4) | (lane >> 1);   // tag owned by lane pair
    const int half = lane & 1;                        // which i-half
    const int b = blockIdx.x;

    int len = lengths[b];
    len = len < 1 ? 1 : (len > T ? T : len);

    const size_t bstride = (size_t)T * K_;
    const float* ub = unary + (size_t)b * bstride;
    float* arow = g_alpha + (size_t)b * bstride;

    const uint32_t su_base = (uint32_t)__cvta_generic_to_shared(&s_u[0][0][0]);

    // ---- prefetch first unary chunk (steps 1..8 -> rows 0..7) ----
    {
        int s = tid >> 4;
        int c = (tid & 15) * 4;
        int row = s; if (row > T - 1) row = T - 1;
        cp_async16(su_base + (uint32_t)(s * K_ + c) * 4,
                   ub + (size_t)row * K_ + c);
        cp_commit();
    }

    // Shared transposed table (cooperative copy, 128 threads x 8 float4).
    {
        const float4* src = (const float4*)g_transT;
        float4* dst = (float4*)s_transT;
        #pragma unroll
        for (int q = 0; q < 8; q++) dst[tid + q * 128] = src[tid + q * 128];
    }

    // Transition half-column for (j, half): 16 packed pairs over
    // i = 32*half + 2q, 2q+1.
    ull ttr[16];
    {
        const int i0 = half << 5;
        #pragma unroll
        for (int q = 0; q < 16; q++) {
            unsigned lo = __float_as_uint(g_trans[(i0 + 2 * q) * K_ + j]);
            unsigned hi = __float_as_uint(g_trans[(i0 + 2 * q + 1) * K_ + j]);
            ttr[q] = ((ull)hi << 32) | lo;
        }
    }

    if (half == 0) s_alpha[0][j] = (j == GO_TAG) ? 0.0f : NEGV;
    __syncthreads();

    // -------------------- forward --------------------
    int cbuf = 0;
    for (int t0 = 1; t0 <= len; t0 += 8) {
        if (t0 + 8 <= len) {
            int s = tid >> 4;
            int c = (tid & 15) * 4;
            int row = t0 + 7 + s;
            if (row > T - 1) row = T - 1;
            cp_async16(su_base + (uint32_t)(((cbuf ^ 1) * 8 + s) * K_ + c) * 4,
                       ub + (size_t)row * K_ + c);
        }
        cp_commit();
        cp_wait<1>();
        __syncthreads();

        #pragma unroll
        for (int s = 0; s < 8; s++) {
            const int t = t0 + s;
            if (t <= len) {                  // uniform per block
                const float u = s_u[cbuf][s][j];
                // This thread's 32 alphas (16B loads), 16 packed adds.
                const ulonglong2* av =
                    (const ulonglong2*)(s_alpha[(t - 1) & 1] + (half << 5));
                float ch[8];
                #pragma unroll
                for (int k = 0; k < 8; k++) {
                    ulonglong2 p = av[k];
                    ull s0 = add2(p.x, ttr[2 * k]);
                    ull s1 = add2(p.y, ttr[2 * k + 1]);
                    float l0, h0, l1, h1;
                    unpack2(s0, l0, h0);
                    unpack2(s1, l1, h1);
                    const int c4 = (k & 1) * 4;
                    if (k < 2) {
                        ch[c4 + 0] = l0; ch[c4 + 1] = h0;
                        ch[c4 + 2] = l1; ch[c4 + 3] = h1;
                    } else {
                        ch[c4 + 0] = fmaxf(ch[c4 + 0], l0);
                        ch[c4 + 1] = fmaxf(ch[c4 + 1], h0);
                        ch[c4 + 2] = fmaxf(ch[c4 + 2], l1);
                        ch[c4 + 3] = fmaxf(ch[c4 + 3], h1);
                    }
                }
                float m01 = fmaxf(ch[0], ch[1]);
                float m23 = fmaxf(ch[2], ch[3]);
                float m45 = fmaxf(ch[4], ch[5]);
                float m67 = fmaxf(ch[6], ch[7]);
                float m = fmaxf(fmaxf(m01, m23), fmaxf(m45, m67));
                // Combine the two i-halves within the lane pair.
                m = fmaxf(m, __shfl_xor_sync(0xffffffffu, m, 1));
                const float a = m + u;
                if (half == 0) {
                    s_alpha[t & 1][j] = a;
                    if (t < len) arow[(size_t)t * K_ + j] = a;  // rows 1..len-1
                }
                __syncthreads();
            }
        }
        cbuf ^= 1;
    }

    // last = argmax_j(final alpha), first-index tiebreak (exact scan).
    if (tid == 0) {
        const float* af = s_alpha[len & 1];
        float bv = af[0];
        int bi = 0;
        #pragma unroll
        for (int i = 1; i < K_; i++) {
            if (af[i] > bv) { bv = af[i]; bi = i; }
        }
        s_last = bi;
    }
    __syncthreads();
    const int last = s_last;

    // Output positions tau >= len-1 all equal `last`.
    float* ob = out + (size_t)b * T;
    const float lastf = (float)last;
    for (int tau = (len - 1) + tid; tau < T; tau += 128) ob[tau] = lastf;

    // -------------------- backward (warp 0) --------------------
    if (tid < 32 && len >= 2) {
        int tag = last;

        #pragma unroll
        for (int rr = 0; rr < 4; rr++) {
            int l = lane + rr * 32;
            int s = l >> 4;
            int c = (l & 15) * 4;
            int row = len - 1 - s; if (row < 0) row = 0;
            cp_async16(su_base + (uint32_t)(s * K_ + c) * 4,
                       arow + (size_t)row * K_ + c);
        }
        cp_commit();

        int bbuf = 0;
        for (int tb = len; tb >= 2; tb -= 8) {
            if (tb - 8 >= 2) {
                #pragma unroll
                for (int rr = 0; rr < 4; rr++) {
                    int l = lane + rr * 32;
                    int s = l >> 4;
                    int c = (l & 15) * 4;
                    int row = tb - 9 - s; if (row < 0) row = 0;
                    cp_async16(su_base + (uint32_t)(((bbuf ^ 1) * 8 + s) * K_ + c) * 4,
                               arow + (size_t)row * K_ + c);
                }
            }
            cp_commit();
            cp_wait<1>();
            __syncwarp();

            const int tlo = (tb - 7 > 2) ? tb - 7 : 2;
            #pragma unroll
            for (int s = 0; s < 8; s++) {
                const int t = tb - s;
                if (t >= tlo) {
                    float2 a = ((const float2*)&s_u[bbuf][s][0])[lane];
                    float2 tt = ((const float2*)(s_transT + tag * K_))[lane];
                    float c0 = a.x + tt.x;
                    float c1 = a.y + tt.y;
                    float v; int li;
                    if (c0 >= c1) { v = c0; li = 2 * lane; }
                    else          { v = c1; li = 2 * lane + 1; }
                    unsigned bits = __float_as_uint(v);
                    unsigned key = ((int)bits < 0) ? ~bits : (bits | 0x80000000u);
                    unsigned mx = __reduce_max_sync(0xffffffffu, key);
                    unsigned sel = (key == mx) ? (unsigned)(K_ - 1 - li) : 0u;
                    unsigned w = __reduce_max_sync(0xffffffffu, sel);
                    tag = (K_ - 1) - (int)w;
                    if (lane == 0) ob[t - 2] = (float)tag;
                }
            }
            bbuf ^= 1;
        }
    }
}

extern "C" void kernel_launch(void* const* d_in, const int* in_sizes, int n_in,
                              void* d_out, int out_size) {
    // ----- identify inputs by SIZE, not position -----
    int iu = 0;
    for (int i = 1; i < n_in; i++)
        if (in_sizes[i] > in_sizes[iu]) iu = i;

    int pair[2] = {-1, -1};
    int ilen = -1;
    for (int i = 0; i < n_in; i++) {
        if (i == iu) continue;
        for (int k = 0; k < n_in; k++) {
            if (k == i || k == iu) continue;
            if (in_sizes[k] == in_sizes[i]) { pair[0] = i < k ? i : k; pair[1] = i < k ? k : i; }
        }
    }
    for (int i = 0; i < n_in; i++)
        if (i != iu && i != pair[0] && i != pair[1]) ilen = i;
    if (ilen < 0) { iu = 0; ilen = 1; pair[0] = 2; pair[1] = 3; }

    const float* unary   = (const float*)d_in[iu];
    const int*   lengths = (const int*)d_in[ilen];
    const float* c0      = (const float*)d_in[pair[0]];
    const float* c1      = (const float*)d_in[pair[1]];
    float* out = (float*)d_out;

    const int B = in_sizes[ilen];
    const int T = (int)((long long)in_sizes[iu] / ((long long)B * K_));

    trans_kernel<<<K_, K_>>>(c0, c1);
    viterbi_kernel<<<B, 128>>>(unary, lengths, out, T, B);
}

// round 10
// speedup vs baseline: 1.4755x; 1.4755x over previous
#include <cuda_runtime.h>
#include <cstdint>
#include <math.h>

#define GO_TAG 1
#define NEGV   -10000.0f
#define K_     64
#define MAXELEMS_ (1024u * 512u * 64u)
#define ORDER_MAX 65536
#define NWORK_BLOCKS 444   // 3 per SM on 148-SM GB300

// Scratch: alpha history rows 1..len-1 per batch, trans tables, scheduler.
__device__ float g_trans[K_ * K_];    // trans[i][j] = score(i -> j)
__device__ float g_transT[K_ * K_];   // transT[j][i] = trans[i][j]
__device__ float g_alpha[MAXELEMS_];
__device__ int   g_ctr;
__device__ int   g_order[ORDER_MAX];

__device__ __forceinline__ void cp_async16(uint32_t saddr, const void* gptr) {
    asm volatile("cp.async.ca.shared.global [%0], [%1], 16;"
                 :: "r"(saddr), "l"(gptr));
}
__device__ __forceinline__ void cp_commit() {
    asm volatile("cp.async.commit_group;");
}
template <int N>
__device__ __forceinline__ void cp_wait() {
    asm volatile("cp.async.wait_group %0;" :: "n"(N));
}

// ---------------------------------------------------------------------------
// Kernel 1: trans = log_softmax(A + mask * NEG, axis=-1) + transpose.
// ---------------------------------------------------------------------------
__global__ void __launch_bounds__(64)
trans_kernel(const float* __restrict__ c0, const float* __restrict__ c1) {
    __shared__ float  s_m[2];
    __shared__ double s_s[2];
    const int r = blockIdx.x;
    const int c = threadIdx.x;
    const int w = c >> 5;
    const int lane = c & 31;

    unsigned u0 = ((const unsigned*)c0)[r * K_ + c];
    const bool c0_is_mask = __syncthreads_and(u0 <= 1u);
    const int*   mask = (const int*)(c0_is_mask ? c0 : c1);
    const float* A    = c0_is_mask ? c1 : c0;

    float x = A[r * K_ + c] + (mask[r * K_ + c] ? NEGV : 0.0f);

    float m = x;
    #pragma unroll
    for (int d = 16; d > 0; d >>= 1) m = fmaxf(m, __shfl_xor_sync(~0u, m, d));
    if (lane == 0) s_m[w] = m;
    __syncthreads();
    m = fmaxf(s_m[0], s_m[1]);

    double e = exp((double)(x - m));
    #pragma unroll
    for (int d = 16; d > 0; d >>= 1) e += __shfl_xor_sync(~0u, e, d);
    if (lane == 0) s_s[w] = e;
    __syncthreads();
    const float l = (float)log(s_s[0] + s_s[1]);

    const float v = (x - m) - l;
    g_trans[r * K_ + c]  = v;
    g_transT[c * K_ + r] = v;
}

// ---------------------------------------------------------------------------
// Kernel 1b: counting-sort sequence indices by DESCENDING length (LPT order)
// into g_order; also resets the work counter. 1 block, 1024 threads.
// ---------------------------------------------------------------------------
__global__ void __launch_bounds__(1024)
sort_kernel(const int* __restrict__ lengths, int T, int B) {
    __shared__ int h[1024];
    __shared__ int h2[1024];
    __shared__ int cur[1024];
    const int tid = threadIdx.x;
    if (tid == 0) g_ctr = 0;
    h[tid] = 0;
    __syncthreads();

    for (int i = tid; i < B; i += 1024) {
        int len = lengths[i]; len = len < 1 ? 1 : (len > T ? T : len);
        int key = T - len; key = key < 0 ? 0 : (key > 1023 ? 1023 : key);
        atomicAdd(&h[key], 1);
    }
    __syncthreads();

    const int cnt = h[tid];
    // Inclusive Hillis-Steele scan over 1024 bins (double-buffered).
    int* src = h;
    int* dst = h2;
    for (int d = 1; d < 1024; d <<= 1) {
        int v = src[tid];
        if (tid >= d) v += src[tid - d];
        dst[tid] = v;
        __syncthreads();
        int* tmp = src; src = dst; dst = tmp;
    }
    cur[tid] = src[tid] - cnt;   // exclusive prefix = scatter base
    __syncthreads();

    for (int i = tid; i < B; i += 1024) {
        int len = lengths[i]; len = len < 1 ? 1 : (len > T ? T : len);
        int key = T - len; key = key < 0 ? 0 : (key > 1023 ? 1023 : key);
        int pos = atomicAdd(&cur[key], 1);
        if (pos < ORDER_MAX) g_order[pos] = i;
    }
}

// ---------------------------------------------------------------------------
// Kernel 2: PERSISTENT fused Viterbi. Each 128-thread block = 2 independent
// 64-thread groups; each group repeatedly claims the next sequence (LPT order)
// from a global counter. Per sequence: R5's forward (reg-resident trans
// column, smem alpha ping-pong, cp.async unary staging) + path-only backward.
// ---------------------------------------------------------------------------
__global__ void __launch_bounds__(128)
viterbi_kernel(const float* __restrict__ unary,
               const int* __restrict__ lengths,
               float* __restrict__ out,
               int T, int B) {
    __shared__ __align__(16) float s_transT[K_ * K_];
    __shared__ __align__(16) float s_alpha[2][2][K_];   // [g][buf][j]
    __shared__ __align__(16) float s_u[2][2][8][K_];    // [g][buf][s][j]
    __shared__ int s_last[2];
    __shared__ int s_idx[2];

    const int tid = threadIdx.x;
    const int g = tid >> 6;
    const int j = tid & 63;
    const int nbar = 1 + g;

    #define GBAR() asm volatile("bar.sync %0, 64;" :: "r"(nbar) : "memory")

    const uint32_t su_base =
        (uint32_t)__cvta_generic_to_shared(&s_u[g][0][0][0]);
    const size_t bstride = (size_t)T * K_;

    // One-time: shared transposed table + register transition column.
    {
        const float4* src = (const float4*)g_transT;
        float4* dst = (float4*)s_transT;
        #pragma unroll
        for (int q = 0; q < 8; q++) dst[tid + q * 128] = src[tid + q * 128];
    }
    float tr[K_];
    #pragma unroll
    for (int i = 0; i < K_; i++) tr[i] = g_trans[i * K_ + j];
    __syncthreads();

    // -------------------- persistent work loop --------------------
    for (;;) {
        if (j == 0) s_idx[g] = atomicAdd(&g_ctr, 1);
        GBAR();
        const int idx = s_idx[g];
        if (idx >= B) break;                 // uniform per group
        const int b = g_order[idx];

        int len = lengths[b];
        len = len < 1 ? 1 : (len > T ? T : len);
        const float* ub = unary + (size_t)b * bstride;
        float* arow = g_alpha + (size_t)b * bstride;

        // Prefetch first unary chunk (steps 1..8 -> rows 0..7, clamped).
        {
            #pragma unroll
            for (int rr = 0; rr < 2; rr++) {
                int l = j + rr * 64;
                int s = l >> 4;
                int c = (l & 15) * 4;
                int row = s; if (row > T - 1) row = T - 1;
                cp_async16(su_base + (uint32_t)(s * K_ + c) * 4,
                           ub + (size_t)row * K_ + c);
            }
            cp_commit();
        }

        s_alpha[g][0][j] = (j == GO_TAG) ? 0.0f : NEGV;
        GBAR();

        // ---------------- forward ----------------
        int cbuf = 0;
        for (int t0 = 1; t0 <= len; t0 += 8) {
            if (t0 + 8 <= len) {
                #pragma unroll
                for (int rr = 0; rr < 2; rr++) {
                    int l = j + rr * 64;
                    int s = l >> 4;
                    int c = (l & 15) * 4;
                    int row = t0 + 7 + s;
                    if (row > T - 1) row = T - 1;
                    cp_async16(su_base + (uint32_t)(((cbuf ^ 1) * 8 + s) * K_ + c) * 4,
                               ub + (size_t)row * K_ + c);
                }
            }
            cp_commit();      // always commit (possibly empty)
            cp_wait<1>();     // current chunk complete
            GBAR();

            const int tend = (t0 + 7 < len) ? t0 + 7 : len;
            #pragma unroll
            for (int s = 0; s < 8; s++) {
                const int t = t0 + s;
                if (t <= tend) {             // uniform per group
                    const float u = s_u[g][cbuf][s][j];
                    const float4* av = (const float4*)s_alpha[g][(t - 1) & 1];
                    float4 v = av[0];
                    float m0 = v.x + tr[0];
                    float m1 = v.y + tr[1];
                    float m2 = v.z + tr[2];
                    float m3 = v.w + tr[3];
                    #pragma unroll
                    for (int q = 1; q < 16; q++) {
                        v = av[q];
                        m0 = fmaxf(m0, v.x + tr[4 * q + 0]);
                        m1 = fmaxf(m1, v.y + tr[4 * q + 1]);
                        m2 = fmaxf(m2, v.z + tr[4 * q + 2]);
                        m3 = fmaxf(m3, v.w + tr[4 * q + 3]);
                    }
                    float a = fmaxf(fmaxf(m0, m1), fmaxf(m2, m3)) + u;
                    s_alpha[g][t & 1][j] = a;
                    if (t < len) arow[(size_t)t * K_ + j] = a;  // rows 1..len-1
                    GBAR();
                }
            }
            cbuf ^= 1;
        }

        // last = argmax_j(final alpha), first-index tiebreak (exact scan).
        if (j == 0) {
            const float* af = s_alpha[g][len & 1];
            float bv = af[0];
            int bi = 0;
            #pragma unroll
            for (int i = 1; i < K_; i++) {
                if (af[i] > bv) { bv = af[i]; bi = i; }
            }
            s_last[g] = bi;
        }
        GBAR();
        const int last = s_last[g];

        // Output positions tau >= len-1 all equal `last`.
        float* ob = out + (size_t)b * T;
        const float lastf = (float)last;
        for (int tau = (len - 1) + j; tau < T; tau += K_) ob[tau] = lastf;

        // ---------------- backward (warp 0 of group) ----------------
        if (j < 32 && len >= 2) {
            const int lane = j;
            int tag = last;

            #pragma unroll
            for (int rr = 0; rr < 4; rr++) {
                int l = lane + rr * 32;
                int s = l >> 4;
                int c = (l & 15) * 4;
                int row = len - 1 - s; if (row < 0) row = 0;
                cp_async16(su_base + (uint32_t)(s * K_ + c) * 4,
                           arow + (size_t)row * K_ + c);
            }
            cp_commit();

            int bbuf = 0;
            for (int tb = len; tb >= 2; tb -= 8) {
                if (tb - 8 >= 2) {
                    #pragma unroll
                    for (int rr = 0; rr < 4; rr++) {
                        int l = lane + rr * 32;
                        int s = l >> 4;
                        int c = (l & 15) * 4;
                        int row = tb - 9 - s; if (row < 0) row = 0;
                        cp_async16(su_base + (uint32_t)(((bbuf ^ 1) * 8 + s) * K_ + c) * 4,
                                   arow + (size_t)row * K_ + c);
                    }
                }
                cp_commit();
                cp_wait<1>();
                __syncwarp();

                const int tlo = (tb - 7 > 2) ? tb - 7 : 2;
                #pragma unroll
                for (int s = 0; s < 8; s++) {
                    const int t = tb - s;
                    if (t >= tlo) {
                        float2 a = ((const float2*)&s_u[g][bbuf][s][0])[lane];
                        float2 tt = ((const float2*)(s_transT + tag * K_))[lane];
                        float c0 = a.x + tt.x;
                        float c1 = a.y + tt.y;
                        float v; int li;
                        if (c0 >= c1) { v = c0; li = 2 * lane; }
                        else          { v = c1; li = 2 * lane + 1; }
                        unsigned bits = __float_as_uint(v);
                        unsigned key = ((int)bits < 0) ? ~bits
                                                       : (bits | 0x80000000u);
                        unsigned mx = __reduce_max_sync(0xffffffffu, key);
                        unsigned sel = (key == mx) ? (unsigned)(K_ - 1 - li) : 0u;
                        unsigned w = __reduce_max_sync(0xffffffffu, sel);
                        tag = (K_ - 1) - (int)w;
                        if (lane == 0) ob[t - 2] = (float)tag;
                    }
                }
                bbuf ^= 1;
            }
        }
        // Protect s_u[g] reuse: warp 1 must not prefetch the next sequence
        // while warp 0 still reads the backward stage.
        GBAR();
    }
    #undef GBAR
}

extern "C" void kernel_launch(void* const* d_in, const int* in_sizes, int n_in,
                              void* d_out, int out_size) {
    // ----- identify inputs by SIZE, not position -----
    int iu = 0;
    for (int i = 1; i < n_in; i++)
        if (in_sizes[i] > in_sizes[iu]) iu = i;

    int pair[2] = {-1, -1};
    int ilen = -1;
    for (int i = 0; i < n_in; i++) {
        if (i == iu) continue;
        for (int k = 0; k < n_in; k++) {
            if (k == i || k == iu) continue;
            if (in_sizes[k] == in_sizes[i]) { pair[0] = i < k ? i : k; pair[1] = i < k ? k : i; }
        }
    }
    for (int i = 0; i < n_in; i++)
        if (i != iu && i != pair[0] && i != pair[1]) ilen = i;
    if (ilen < 0) { iu = 0; ilen = 1; pair[0] = 2; pair[1] = 3; }

    const float* unary   = (const float*)d_in[iu];
    const int*   lengths = (const int*)d_in[ilen];
    const float* c0      = (const float*)d_in[pair[0]];
    const float* c1      = (const float*)d_in[pair[1]];
    float* out = (float*)d_out;

    const int B = in_sizes[ilen];
    const int T = (int)((long long)in_sizes[iu] / ((long long)B * K_));

    trans_kernel<<<K_, K_>>>(c0, c1);
    sort_kernel<<<1, 1024>>>(lengths, T, B);
    viterbi_kernel<<<NWORK_BLOCKS, 128>>>(unary, lengths, out, T, B);
}